// round 1
// baseline (speedup 1.0000x reference)
#include <cuda_runtime.h>
#include <cstdint>

#define Bq 8
#define Nq 1024
#define Dq 256
#define Hq 8
#define Uq 64
#define HU 512

// -------- scratch (device globals; no allocation in kernel_launch) --------
__device__ float g_feat[Bq * Nq * HU];   // features
__device__ float g_fres[Bq * Nq * HU];   // residual features
__device__ float g_as[Bq * Nq * Hq];     // attn_self logits
__device__ float g_an[Bq * Nq * Hq];     // attn_neigh logits

// ---------------- Kernel 1: fp32 tiled SGEMM  out = X @ W ----------------
// M=8192, N=512, K=256. Block tile 128x64, K-tile 16, 256 threads, 8x4/thread.
__global__ __launch_bounds__(256) void sgemm_k(const float* __restrict__ Xg,
                                               const float* __restrict__ Wg,
                                               int which) {
    __shared__ float As[16][128];
    __shared__ float Bs[16][64];
    float* out = which ? g_fres : g_feat;

    const int tid = threadIdx.x;
    const int m0 = blockIdx.y * 128;
    const int n0 = blockIdx.x * 64;
    const int tx = tid & 15;   // -> n (x4)
    const int ty = tid >> 4;   // -> m (x8)

    float acc[8][4];
#pragma unroll
    for (int i = 0; i < 8; i++)
#pragma unroll
        for (int j = 0; j < 4; j++) acc[i][j] = 0.0f;

    const int a_m  = tid >> 2;   // 0..63
    const int a_k4 = tid & 3;    // 0..3  (k offset *4)
    const int b_k  = tid >> 4;   // 0..15
    const int b_n4 = tid & 15;   // 0..15 (n offset *4)

    for (int k0 = 0; k0 < Dq; k0 += 16) {
#pragma unroll
        for (int r = 0; r < 2; r++) {
            int m = a_m + r * 64;
            float4 v = *(const float4*)&Xg[(size_t)(m0 + m) * Dq + k0 + a_k4 * 4];
            As[a_k4 * 4 + 0][m] = v.x;
            As[a_k4 * 4 + 1][m] = v.y;
            As[a_k4 * 4 + 2][m] = v.z;
            As[a_k4 * 4 + 3][m] = v.w;
        }
        float4 w = *(const float4*)&Wg[(size_t)(k0 + b_k) * HU + n0 + b_n4 * 4];
        *(float4*)&Bs[b_k][b_n4 * 4] = w;
        __syncthreads();
#pragma unroll
        for (int k = 0; k < 16; k++) {
            float4 a0 = *(const float4*)&As[k][ty * 8];
            float4 a1 = *(const float4*)&As[k][ty * 8 + 4];
            float4 bv = *(const float4*)&Bs[k][tx * 4];
            float av[8] = {a0.x, a0.y, a0.z, a0.w, a1.x, a1.y, a1.z, a1.w};
            float bw[4] = {bv.x, bv.y, bv.z, bv.w};
#pragma unroll
            for (int i = 0; i < 8; i++)
#pragma unroll
                for (int j = 0; j < 4; j++) acc[i][j] += av[i] * bw[j];
        }
        __syncthreads();
    }
#pragma unroll
    for (int i = 0; i < 8; i++) {
        float4 v = make_float4(acc[i][0], acc[i][1], acc[i][2], acc[i][3]);
        *(float4*)&out[(size_t)(m0 + ty * 8 + i) * HU + n0 + tx * 4] = v;
    }
}

// --------- Kernel 2: attention logits (one warp per (b,n,h)) -------------
__global__ __launch_bounds__(256) void attn_logits_k(const float* __restrict__ aks,
                                                     const float* __restrict__ akn) {
    int gwarp = (blockIdx.x * blockDim.x + threadIdx.x) >> 5;
    int lane = threadIdx.x & 31;
    if (gwarp >= Bq * Nq * Hq) return;
    int h = gwarp % Hq;
    int bn = gwarp / Hq;
    const float* fp = g_feat + (size_t)bn * HU + h * Uq;
    float f0 = fp[lane], f1 = fp[lane + 32];
    float s = f0 * aks[h * Uq + lane] + f1 * aks[h * Uq + lane + 32];
    float nn = f0 * akn[h * Uq + lane] + f1 * akn[h * Uq + lane + 32];
#pragma unroll
    for (int o = 16; o; o >>= 1) {
        s  += __shfl_xor_sync(0xffffffffu, s, o);
        nn += __shfl_xor_sync(0xffffffffu, nn, o);
    }
    if (lane == 0) {
        g_as[gwarp] = s;
        g_an[gwarp] = nn;
    }
}

// --------- Kernel 3: per-row masked softmax + sparse aggregation ---------
// grid (H, N, B), 64 threads; thread t owns unit u = t.
__global__ __launch_bounds__(64) void gat_row_k(const float* __restrict__ A,
                                                const float* __restrict__ fres_unused,
                                                const float* __restrict__ bias,
                                                float* __restrict__ out) {
    const int h = blockIdx.x;
    const int n = blockIdx.y;
    const int b = blockIdx.z;
    const int t = threadIdx.x;

    __shared__ int   s_idx[Nq];
    __shared__ float s_lg[Nq];
    __shared__ int   s_cnt;
    __shared__ float s_wred[2];
    if (t == 0) s_cnt = 0;
    __syncthreads();

    const float aself = g_as[((size_t)b * Nq + n) * Hq + h];
    const float4* A4 = (const float4*)(A + ((size_t)b * Nq + n) * Nq);

    float lmax = -1e30f;
#pragma unroll
    for (int i = 0; i < 4; i++) {
        int k4 = t + i * 64;        // 0..255
        float4 a = A4[k4];
        float av[4] = {a.x, a.y, a.z, a.w};
        int kb = k4 * 4;
#pragma unroll
        for (int j = 0; j < 4; j++) {
            if (av[j] > 0.0f) {
                int k = kb + j;
                float x = aself + g_an[((size_t)b * Nq + k) * Hq + h];
                float lr = x > 0.0f ? x : 0.2f * x;
                int p = atomicAdd(&s_cnt, 1);
                s_idx[p] = k;
                s_lg[p] = lr;
                lmax = fmaxf(lmax, lr);
            }
        }
    }
#pragma unroll
    for (int o = 16; o; o >>= 1) lmax = fmaxf(lmax, __shfl_xor_sync(0xffffffffu, lmax, o));
    if ((t & 31) == 0) s_wred[t >> 5] = lmax;
    __syncthreads();
    const float m = fmaxf(s_wred[0], s_wred[1]);
    const int cnt = s_cnt;
    __syncthreads();

    float lsum = 0.0f;
    for (int j = t; j < cnt; j += 64) {
        float w = __expf(s_lg[j] - m);
        s_lg[j] = w;
        lsum += w;
    }
#pragma unroll
    for (int o = 16; o; o >>= 1) lsum += __shfl_xor_sync(0xffffffffu, lsum, o);
    if ((t & 31) == 0) s_wred[t >> 5] = lsum;
    __syncthreads();
    const float ssum = s_wred[0] + s_wred[1];

    // aggregate: acc[u=t] = sum_j w_j * feat[b, k_j, h, t]
    const float* fb = g_feat + (size_t)b * Nq * HU + h * Uq + t;
    float acc = 0.0f;
    int j = 0;
    for (; j + 4 <= cnt; j += 4) {
        int k0 = s_idx[j], k1 = s_idx[j + 1], k2 = s_idx[j + 2], k3 = s_idx[j + 3];
        float w0 = s_lg[j], w1 = s_lg[j + 1], w2 = s_lg[j + 2], w3 = s_lg[j + 3];
        float v0 = fb[(size_t)k0 * HU];
        float v1 = fb[(size_t)k1 * HU];
        float v2 = fb[(size_t)k2 * HU];
        float v3 = fb[(size_t)k3 * HU];
        acc += w0 * v0 + w1 * v1 + w2 * v2 + w3 * v3;
    }
    for (; j < cnt; j++) acc += s_lg[j] * fb[(size_t)s_idx[j] * HU];

    const size_t oidx = ((size_t)b * Nq + n) * HU + h * Uq + t;
    float o = acc / ssum + g_fres[oidx] + bias[h * Uq + t];
    out[oidx] = fmaxf(o, 0.0f);
}

// -------------------------------- launch ---------------------------------
extern "C" void kernel_launch(void* const* d_in, const int* in_sizes, int n_in,
                              void* d_out, int out_size) {
    const float* X   = (const float*)d_in[0];
    const float* A   = (const float*)d_in[1];
    const float* Wk  = (const float*)d_in[2];
    const float* Wr  = (const float*)d_in[3];
    const float* aks = (const float*)d_in[4];
    const float* akn = (const float*)d_in[5];
    const float* bias = (const float*)d_in[6];
    float* out = (float*)d_out;

    dim3 ggrid(HU / 64, (Bq * Nq) / 128);
    sgemm_k<<<ggrid, 256>>>(X, Wk, 0);
    sgemm_k<<<ggrid, 256>>>(X, Wr, 1);

    int nwarps = Bq * Nq * Hq;                 // 65536
    attn_logits_k<<<(nwarps * 32) / 256, 256>>>(aks, akn);

    gat_row_k<<<dim3(Hq, Nq, Bq), 64>>>(A, nullptr, bias, out);
}

// round 2
// speedup vs baseline: 1.1242x; 1.1242x over previous
#include <cuda_runtime.h>
#include <cstdint>

#define Bq 8
#define Nq 1024
#define Dq 256
#define Hq 8
#define Uq 64
#define HU 512
#define WPAD 1025   // s_w pitch (1025 % 32 == 1 -> conflict-light both phases)

// -------- scratch (device globals; no allocation in kernel_launch) --------
__device__ float g_feat[Bq * Nq * HU];   // features
__device__ float g_fres[Bq * Nq * HU];   // residual features
__device__ float g_as[Bq * Nq * Hq];     // attn_self logits
__device__ float g_an[Bq * Nq * Hq];     // attn_neigh logits

// ---------------- Kernel 1: fp32 tiled SGEMM  out = X @ W ----------------
// M=8192, N=512, K=256. Block tile 128x64, K-tile 16, 256 threads, 8x4/thread.
__global__ __launch_bounds__(256) void sgemm_k(const float* __restrict__ Xg,
                                               const float* __restrict__ Wg,
                                               int which) {
    __shared__ float As[16][128];
    __shared__ float Bs[16][64];
    float* out = which ? g_fres : g_feat;

    const int tid = threadIdx.x;
    const int m0 = blockIdx.y * 128;
    const int n0 = blockIdx.x * 64;
    const int tx = tid & 15;   // -> n (x4)
    const int ty = tid >> 4;   // -> m (x8)

    float acc[8][4];
#pragma unroll
    for (int i = 0; i < 8; i++)
#pragma unroll
        for (int j = 0; j < 4; j++) acc[i][j] = 0.0f;

    const int a_m  = tid >> 2;   // 0..63
    const int a_k4 = tid & 3;    // 0..3  (k offset *4)
    const int b_k  = tid >> 4;   // 0..15
    const int b_n4 = tid & 15;   // 0..15 (n offset *4)

    for (int k0 = 0; k0 < Dq; k0 += 16) {
#pragma unroll
        for (int r = 0; r < 2; r++) {
            int m = a_m + r * 64;
            float4 v = *(const float4*)&Xg[(size_t)(m0 + m) * Dq + k0 + a_k4 * 4];
            As[a_k4 * 4 + 0][m] = v.x;
            As[a_k4 * 4 + 1][m] = v.y;
            As[a_k4 * 4 + 2][m] = v.z;
            As[a_k4 * 4 + 3][m] = v.w;
        }
        float4 w = *(const float4*)&Wg[(size_t)(k0 + b_k) * HU + n0 + b_n4 * 4];
        *(float4*)&Bs[b_k][b_n4 * 4] = w;
        __syncthreads();
#pragma unroll
        for (int k = 0; k < 16; k++) {
            float4 a0 = *(const float4*)&As[k][ty * 8];
            float4 a1 = *(const float4*)&As[k][ty * 8 + 4];
            float4 bv = *(const float4*)&Bs[k][tx * 4];
            float av[8] = {a0.x, a0.y, a0.z, a0.w, a1.x, a1.y, a1.z, a1.w};
            float bw[4] = {bv.x, bv.y, bv.z, bv.w};
#pragma unroll
            for (int i = 0; i < 8; i++)
#pragma unroll
                for (int j = 0; j < 4; j++) acc[i][j] += av[i] * bw[j];
        }
        __syncthreads();
    }
#pragma unroll
    for (int i = 0; i < 8; i++) {
        float4 v = make_float4(acc[i][0], acc[i][1], acc[i][2], acc[i][3]);
        *(float4*)&out[(size_t)(m0 + ty * 8 + i) * HU + n0 + tx * 4] = v;
    }
}

// --------- Kernel 2: attention logits (one warp per (b,n,h)) -------------
__global__ __launch_bounds__(256) void attn_logits_k(const float* __restrict__ aks,
                                                     const float* __restrict__ akn) {
    int gwarp = (blockIdx.x * blockDim.x + threadIdx.x) >> 5;
    int lane = threadIdx.x & 31;
    if (gwarp >= Bq * Nq * Hq) return;
    int h = gwarp % Hq;
    int bn = gwarp / Hq;
    const float* fp = g_feat + (size_t)bn * HU + h * Uq;
    float f0 = fp[lane], f1 = fp[lane + 32];
    float s = f0 * aks[h * Uq + lane] + f1 * aks[h * Uq + lane + 32];
    float nn = f0 * akn[h * Uq + lane] + f1 * akn[h * Uq + lane + 32];
#pragma unroll
    for (int o = 16; o; o >>= 1) {
        s  += __shfl_xor_sync(0xffffffffu, s, o);
        nn += __shfl_xor_sync(0xffffffffu, nn, o);
    }
    if (lane == 0) {
        g_as[gwarp] = s;
        g_an[gwarp] = nn;
    }
}

// --------- Kernel 3: fused all-heads masked softmax + aggregation ---------
// grid (N, B), 512 threads. Thread t: h = t>>6, u = t&63.
__global__ __launch_bounds__(512) void gat_row_k(const float* __restrict__ A,
                                                 const float* __restrict__ bias,
                                                 float* __restrict__ out) {
    const int n = blockIdx.x;
    const int b = blockIdx.y;
    const int t = threadIdx.x;
    const int lane = t & 31;
    const int wid = t >> 5;     // 0..15
    const int h = t >> 6;       // 0..7
    const int u = t & 63;

    __shared__ int   s_idx[Nq];
    __shared__ float s_w[Hq][WPAD];
    __shared__ float s_red[16];
    __shared__ float s_as[Hq];
    __shared__ int   s_cnt;
    if (t == 0) s_cnt = 0;
    if (t < Hq) s_as[t] = g_as[((size_t)b * Nq + n) * Hq + t];
    __syncthreads();

    // ---- Phase 1: build compact edge list (ballot + warp-aggregated atomic)
    const float* Arow = A + ((size_t)b * Nq + n) * Nq;
    {
#pragma unroll
        for (int half = 0; half < 2; half++) {
            int c = half * 512 + t;          // column; warp reads 128B coalesced
            unsigned m = __ballot_sync(0xffffffffu, Arow[c] > 0.0f);
            int cntw = __popc(m);
            int base = 0;
            if (lane == 0 && cntw) base = atomicAdd(&s_cnt, cntw);
            base = __shfl_sync(0xffffffffu, base, 0);
            if (Arow[c] > 0.0f) {
                int off = __popc(m & ((1u << lane) - 1u));
                s_idx[base + off] = c;
            }
        }
    }
    __syncthreads();
    const int cnt = s_cnt;

    // ---- Phase 2: per-(edge, head) leaky-relu logits
    // pair p -> edge j = p>>3, head hh = p&7. 8 consecutive threads read
    // g_an[(b,k),0..7] contiguously (32B).
    const float* anb = g_an + (size_t)b * Nq * Hq;
    for (int p = t; p < cnt * Hq; p += 512) {
        int j = p >> 3;
        int hh = p & 7;
        int k = s_idx[j];
        float x = s_as[hh] + anb[(size_t)k * Hq + hh];
        s_w[hh][j] = (x > 0.0f) ? x : 0.2f * x;
    }
    __syncthreads();

    // ---- Phase 3: per-head max
    float lmax = -1e30f;
    for (int j = u; j < cnt; j += 64) lmax = fmaxf(lmax, s_w[h][j]);
#pragma unroll
    for (int o = 16; o; o >>= 1) lmax = fmaxf(lmax, __shfl_xor_sync(0xffffffffu, lmax, o));
    if (lane == 0) s_red[wid] = lmax;
    __syncthreads();
    const float m = fmaxf(s_red[2 * h], s_red[2 * h + 1]);
    __syncthreads();

    // ---- Phase 4: exp + per-head sum (store exp back)
    float lsum = 0.0f;
    for (int j = u; j < cnt; j += 64) {
        float w = __expf(s_w[h][j] - m);
        s_w[h][j] = w;
        lsum += w;
    }
#pragma unroll
    for (int o = 16; o; o >>= 1) lsum += __shfl_xor_sync(0xffffffffu, lsum, o);
    if (lane == 0) s_red[wid] = lsum;
    __syncthreads();
    const float ssum = s_red[2 * h] + s_red[2 * h + 1];

    // ---- Phase 5: aggregate. Thread t owns output element h*64+u = t.
    // Per edge: all 512 threads read f[b,k,0:512] (2KB, fully coalesced).
    const float* fb = g_feat + (size_t)b * Nq * HU + t;
    float acc = 0.0f;
    int j = 0;
    for (; j + 4 <= cnt; j += 4) {
        int k0 = s_idx[j], k1 = s_idx[j + 1], k2 = s_idx[j + 2], k3 = s_idx[j + 3];
        float w0 = s_w[h][j], w1 = s_w[h][j + 1], w2 = s_w[h][j + 2], w3 = s_w[h][j + 3];
        acc += w0 * fb[(size_t)k0 * HU];
        acc += w1 * fb[(size_t)k1 * HU];
        acc += w2 * fb[(size_t)k2 * HU];
        acc += w3 * fb[(size_t)k3 * HU];
    }
    for (; j < cnt; j++) acc += s_w[h][j] * fb[(size_t)s_idx[j] * HU];

    const size_t oidx = ((size_t)b * Nq + n) * HU + t;
    float o = acc / ssum + g_fres[oidx] + bias[t];
    out[oidx] = fmaxf(o, 0.0f);
}

// -------------------------------- launch ---------------------------------
extern "C" void kernel_launch(void* const* d_in, const int* in_sizes, int n_in,
                              void* d_out, int out_size) {
    const float* X   = (const float*)d_in[0];
    const float* A   = (const float*)d_in[1];
    const float* Wk  = (const float*)d_in[2];
    const float* Wr  = (const float*)d_in[3];
    const float* aks = (const float*)d_in[4];
    const float* akn = (const float*)d_in[5];
    const float* bias = (const float*)d_in[6];
    float* out = (float*)d_out;

    dim3 ggrid(HU / 64, (Bq * Nq) / 128);
    sgemm_k<<<ggrid, 256>>>(X, Wk, 0);
    sgemm_k<<<ggrid, 256>>>(X, Wr, 1);

    int nwarps = Bq * Nq * Hq;                 // 65536
    attn_logits_k<<<(nwarps * 32) / 256, 256>>>(aks, akn);

    gat_row_k<<<dim3(Nq, Bq), 512>>>(A, bias, out);
}

// round 3
// speedup vs baseline: 1.2942x; 1.1512x over previous
#include <cuda_runtime.h>
#include <cstdint>

#define Bq 8
#define Nq 1024
#define Dq 256
#define Hq 8
#define Uq 64
#define HU 512
#define WPAD 1025   // s_w pitch (1025 % 32 == 1 -> conflict-free writes, broadcast reads)

// -------- scratch (device globals; no allocation in kernel_launch) --------
__device__ float g_feat[Bq * Nq * HU];   // features
__device__ float g_fres[Bq * Nq * HU];   // residual features
__device__ float g_as[Bq * Nq * Hq];     // attn_self logits
__device__ float g_an[Bq * Nq * Hq];     // attn_neigh logits

// ---------------- Kernel 1: fp32 tiled SGEMM  out = X @ W ----------------
__global__ __launch_bounds__(256) void sgemm_k(const float* __restrict__ Xg,
                                               const float* __restrict__ Wg,
                                               int which) {
    __shared__ float As[16][128];
    __shared__ float Bs[16][64];
    float* out = which ? g_fres : g_feat;

    const int tid = threadIdx.x;
    const int m0 = blockIdx.y * 128;
    const int n0 = blockIdx.x * 64;
    const int tx = tid & 15;
    const int ty = tid >> 4;

    float acc[8][4];
#pragma unroll
    for (int i = 0; i < 8; i++)
#pragma unroll
        for (int j = 0; j < 4; j++) acc[i][j] = 0.0f;

    const int a_m  = tid >> 2;
    const int a_k4 = tid & 3;
    const int b_k  = tid >> 4;
    const int b_n4 = tid & 15;

    for (int k0 = 0; k0 < Dq; k0 += 16) {
#pragma unroll
        for (int r = 0; r < 2; r++) {
            int m = a_m + r * 64;
            float4 v = *(const float4*)&Xg[(size_t)(m0 + m) * Dq + k0 + a_k4 * 4];
            As[a_k4 * 4 + 0][m] = v.x;
            As[a_k4 * 4 + 1][m] = v.y;
            As[a_k4 * 4 + 2][m] = v.z;
            As[a_k4 * 4 + 3][m] = v.w;
        }
        float4 w = *(const float4*)&Wg[(size_t)(k0 + b_k) * HU + n0 + b_n4 * 4];
        *(float4*)&Bs[b_k][b_n4 * 4] = w;
        __syncthreads();
#pragma unroll
        for (int k = 0; k < 16; k++) {
            float4 a0 = *(const float4*)&As[k][ty * 8];
            float4 a1 = *(const float4*)&As[k][ty * 8 + 4];
            float4 bv = *(const float4*)&Bs[k][tx * 4];
            float av[8] = {a0.x, a0.y, a0.z, a0.w, a1.x, a1.y, a1.z, a1.w};
            float bw[4] = {bv.x, bv.y, bv.z, bv.w};
#pragma unroll
            for (int i = 0; i < 8; i++)
#pragma unroll
                for (int j = 0; j < 4; j++) acc[i][j] += av[i] * bw[j];
        }
        __syncthreads();
    }
#pragma unroll
    for (int i = 0; i < 8; i++) {
        float4 v = make_float4(acc[i][0], acc[i][1], acc[i][2], acc[i][3]);
        *(float4*)&out[(size_t)(m0 + ty * 8 + i) * HU + n0 + tx * 4] = v;
    }
}

// --------- Kernel 2: attention logits (one warp per (b,n,h)) -------------
__global__ __launch_bounds__(256) void attn_logits_k(const float* __restrict__ aks,
                                                     const float* __restrict__ akn) {
    int gwarp = (blockIdx.x * blockDim.x + threadIdx.x) >> 5;
    int lane = threadIdx.x & 31;
    if (gwarp >= Bq * Nq * Hq) return;
    int h = gwarp % Hq;
    int bn = gwarp / Hq;
    const float* fp = g_feat + (size_t)bn * HU + h * Uq;
    float f0 = fp[lane], f1 = fp[lane + 32];
    float s = f0 * aks[h * Uq + lane] + f1 * aks[h * Uq + lane + 32];
    float nn = f0 * akn[h * Uq + lane] + f1 * akn[h * Uq + lane + 32];
#pragma unroll
    for (int o = 16; o; o >>= 1) {
        s  += __shfl_xor_sync(0xffffffffu, s, o);
        nn += __shfl_xor_sync(0xffffffffu, nn, o);
    }
    if (lane == 0) {
        g_as[gwarp] = s;
        g_an[gwarp] = nn;
    }
}

// --------- Kernel 3: fused all-heads masked softmax + aggregation ---------
// grid (N, B), 512 threads.
__global__ __launch_bounds__(512) void gat_row_k(const float* __restrict__ A,
                                                 const float* __restrict__ bias,
                                                 float* __restrict__ out) {
    const int n = blockIdx.x;
    const int b = blockIdx.y;
    const int t = threadIdx.x;
    const int lane = t & 31;
    const int wid = t >> 5;     // 0..15
    const int h = t >> 6;       // 0..7
    const int u = t & 63;

    __shared__ int    s_idx[Nq];
    __shared__ float  s_w[Hq][WPAD];
    __shared__ float  s_red[16];
    __shared__ float  s_sum[Hq];
    __shared__ float  s_as[Hq];
    __shared__ float4 s_acc4[4][128];
    __shared__ int    s_cnt;
    if (t == 0) s_cnt = 0;
    if (t < Hq) s_as[t] = g_as[((size_t)b * Nq + n) * Hq + t];
    __syncthreads();

    // ---- Phase 1: compact edge list (ballot + warp-aggregated atomic)
    const float* Arow = A + ((size_t)b * Nq + n) * Nq;
#pragma unroll
    for (int half = 0; half < 2; half++) {
        int c = half * 512 + t;
        bool e = Arow[c] > 0.0f;
        unsigned m = __ballot_sync(0xffffffffu, e);
        int cntw = __popc(m);
        int base = 0;
        if (lane == 0 && cntw) base = atomicAdd(&s_cnt, cntw);
        base = __shfl_sync(0xffffffffu, base, 0);
        if (e) {
            int off = __popc(m & ((1u << lane) - 1u));
            s_idx[base + off] = c;
        }
    }
    __syncthreads();
    const int cnt = s_cnt;

    // ---- Phase 2: per-(edge, head) leaky-relu logits
    const float* anb = g_an + (size_t)b * Nq * Hq;
    for (int p = t; p < cnt * Hq; p += 512) {
        int j = p >> 3;
        int hh = p & 7;
        int k = s_idx[j];
        float x = s_as[hh] + anb[(size_t)k * Hq + hh];
        s_w[hh][j] = (x > 0.0f) ? x : 0.2f * x;
    }
    __syncthreads();

    // ---- Phase 3: per-head max
    float lmax = -1e30f;
    for (int j = u; j < cnt; j += 64) lmax = fmaxf(lmax, s_w[h][j]);
#pragma unroll
    for (int o = 16; o; o >>= 1) lmax = fmaxf(lmax, __shfl_xor_sync(0xffffffffu, lmax, o));
    if (lane == 0) s_red[wid] = lmax;
    __syncthreads();
    const float m = fmaxf(s_red[2 * h], s_red[2 * h + 1]);
    __syncthreads();

    // ---- Phase 4: exp + per-head sum
    float lsum = 0.0f;
    for (int j = u; j < cnt; j += 64) {
        float w = __expf(s_w[h][j] - m);
        s_w[h][j] = w;
        lsum += w;
    }
#pragma unroll
    for (int o = 16; o; o >>= 1) lsum += __shfl_xor_sync(0xffffffffu, lsum, o);
    if (lane == 0) s_red[wid] = lsum;
    __syncthreads();
    if (lane == 0 && (wid & 1) == 0) s_sum[wid >> 1] = s_red[wid] + s_red[wid + 1];

    // ---- Phase 5: float4 gather. 4 edge sub-slots x 128 float4-columns.
    const int g  = t >> 7;      // 0..3 (edge sub-slot)
    const int c  = t & 127;     // float4 column within the 512-wide row
    const int hc = c >> 4;      // head owning this column
    const float4* f4 = (const float4*)(g_feat + (size_t)b * Nq * HU);
    float4 acc = make_float4(0.f, 0.f, 0.f, 0.f);
    int j = 0;
    for (; j + 4 <= cnt; j += 4) {
        int   k = s_idx[j + g];
        float w = s_w[hc][j + g];
        float4 v = f4[(size_t)k * 128 + c];
        acc.x += w * v.x; acc.y += w * v.y; acc.z += w * v.z; acc.w += w * v.w;
    }
    if (g < cnt - j) {
        int   k = s_idx[j + g];
        float w = s_w[hc][j + g];
        float4 v = f4[(size_t)k * 128 + c];
        acc.x += w * v.x; acc.y += w * v.y; acc.z += w * v.z; acc.w += w * v.w;
    }
    s_acc4[g][c] = acc;
    __syncthreads();

    // ---- Phase 6: reduce sub-slots, add residual + bias, relu, store
    if (t < 128) {
        float4 a0 = s_acc4[0][t], a1 = s_acc4[1][t], a2 = s_acc4[2][t], a3 = s_acc4[3][t];
        float inv = 1.0f / s_sum[t >> 4];
        const size_t row4 = ((size_t)b * Nq + n) * 128 + t;
        float4 fr = ((const float4*)g_fres)[row4];
        float4 bi = ((const float4*)bias)[t];
        float4 o;
        o.x = fmaxf((a0.x + a1.x + a2.x + a3.x) * inv + fr.x + bi.x, 0.0f);
        o.y = fmaxf((a0.y + a1.y + a2.y + a3.y) * inv + fr.y + bi.y, 0.0f);
        o.z = fmaxf((a0.z + a1.z + a2.z + a3.z) * inv + fr.z + bi.z, 0.0f);
        o.w = fmaxf((a0.w + a1.w + a2.w + a3.w) * inv + fr.w + bi.w, 0.0f);
        ((float4*)out)[row4] = o;
    }
}

// -------------------------------- launch ---------------------------------
extern "C" void kernel_launch(void* const* d_in, const int* in_sizes, int n_in,
                              void* d_out, int out_size) {
    const float* X   = (const float*)d_in[0];
    const float* A   = (const float*)d_in[1];
    const float* Wk  = (const float*)d_in[2];
    const float* Wr  = (const float*)d_in[3];
    const float* aks = (const float*)d_in[4];
    const float* akn = (const float*)d_in[5];
    const float* bias = (const float*)d_in[6];
    float* out = (float*)d_out;

    dim3 ggrid(HU / 64, (Bq * Nq) / 128);
    sgemm_k<<<ggrid, 256>>>(X, Wk, 0);
    sgemm_k<<<ggrid, 256>>>(X, Wr, 1);

    int nwarps = Bq * Nq * Hq;
    attn_logits_k<<<(nwarps * 32) / 256, 256>>>(aks, akn);

    gat_row_k<<<dim3(Nq, Bq), 512>>>(A, bias, out);
}

// round 4
// speedup vs baseline: 1.4318x; 1.1063x over previous
#include <cuda_runtime.h>
#include <cstdint>

#define Bq 8
#define Nq 1024
#define Dq 256
#define Hq 8
#define Uq 64
#define HU 512
#define WPAD 1025

// -------- scratch (device globals; no allocation in kernel_launch) --------
__device__ float g_feat[Bq * Nq * HU];   // features
__device__ float g_fres[Bq * Nq * HU];   // residual features
__device__ float g_as[Bq * Nq * Hq];     // attn_self logits
__device__ float g_an[Bq * Nq * Hq];     // attn_neigh logits

// ------- Kernel 1: fused dual SGEMM  g_feat = X@Wk, g_fres = X@Wr --------
// M=8192, N=512(x2), K=256. Tile 128x64, K-tile 16, 256 threads, 8x4x2/thread.
__global__ __launch_bounds__(256) void sgemm_dual_k(const float* __restrict__ Xg,
                                                    const float* __restrict__ Wk,
                                                    const float* __restrict__ Wr) {
    __shared__ float As[16][128];
    __shared__ float BsK[16][64];
    __shared__ float BsR[16][64];

    const int tid = threadIdx.x;
    const int m0 = blockIdx.y * 128;
    const int n0 = blockIdx.x * 64;
    const int tx = tid & 15;
    const int ty = tid >> 4;

    float aK[8][4], aR[8][4];
#pragma unroll
    for (int i = 0; i < 8; i++)
#pragma unroll
        for (int j = 0; j < 4; j++) { aK[i][j] = 0.0f; aR[i][j] = 0.0f; }

    const int a_m  = tid >> 2;
    const int a_k4 = tid & 3;
    const int b_k  = tid >> 4;
    const int b_n4 = tid & 15;

    for (int k0 = 0; k0 < Dq; k0 += 16) {
#pragma unroll
        for (int r = 0; r < 2; r++) {
            int m = a_m + r * 64;
            float4 v = *(const float4*)&Xg[(size_t)(m0 + m) * Dq + k0 + a_k4 * 4];
            As[a_k4 * 4 + 0][m] = v.x;
            As[a_k4 * 4 + 1][m] = v.y;
            As[a_k4 * 4 + 2][m] = v.z;
            As[a_k4 * 4 + 3][m] = v.w;
        }
        size_t widx = (size_t)(k0 + b_k) * HU + n0 + b_n4 * 4;
        *(float4*)&BsK[b_k][b_n4 * 4] = *(const float4*)&Wk[widx];
        *(float4*)&BsR[b_k][b_n4 * 4] = *(const float4*)&Wr[widx];
        __syncthreads();
#pragma unroll
        for (int k = 0; k < 16; k++) {
            float4 a0 = *(const float4*)&As[k][ty * 8];
            float4 a1 = *(const float4*)&As[k][ty * 8 + 4];
            float4 bk = *(const float4*)&BsK[k][tx * 4];
            float4 br = *(const float4*)&BsR[k][tx * 4];
            float av[8] = {a0.x, a0.y, a0.z, a0.w, a1.x, a1.y, a1.z, a1.w};
            float bKv[4] = {bk.x, bk.y, bk.z, bk.w};
            float bRv[4] = {br.x, br.y, br.z, br.w};
#pragma unroll
            for (int i = 0; i < 8; i++)
#pragma unroll
                for (int j = 0; j < 4; j++) {
                    aK[i][j] += av[i] * bKv[j];
                    aR[i][j] += av[i] * bRv[j];
                }
        }
        __syncthreads();
    }
#pragma unroll
    for (int i = 0; i < 8; i++) {
        size_t oidx = (size_t)(m0 + ty * 8 + i) * HU + n0 + tx * 4;
        *(float4*)&g_feat[oidx] = make_float4(aK[i][0], aK[i][1], aK[i][2], aK[i][3]);
        *(float4*)&g_fres[oidx] = make_float4(aR[i][0], aR[i][1], aR[i][2], aR[i][3]);
    }
}

// --------- Kernel 2: attention logits (one warp per (b,n,h)) -------------
__global__ __launch_bounds__(256) void attn_logits_k(const float* __restrict__ aks,
                                                     const float* __restrict__ akn) {
    int gwarp = (blockIdx.x * blockDim.x + threadIdx.x) >> 5;
    int lane = threadIdx.x & 31;
    if (gwarp >= Bq * Nq * Hq) return;
    int h = gwarp % Hq;
    int bn = gwarp / Hq;
    const float* fp = g_feat + (size_t)bn * HU + h * Uq;
    float f0 = fp[lane], f1 = fp[lane + 32];
    float s = f0 * aks[h * Uq + lane] + f1 * aks[h * Uq + lane + 32];
    float nn = f0 * akn[h * Uq + lane] + f1 * akn[h * Uq + lane + 32];
#pragma unroll
    for (int o = 16; o; o >>= 1) {
        s  += __shfl_xor_sync(0xffffffffu, s, o);
        nn += __shfl_xor_sync(0xffffffffu, nn, o);
    }
    if (lane == 0) {
        g_as[gwarp] = s;
        g_an[gwarp] = nn;
    }
}

// --------- Kernel 3: fused all-heads masked softmax + aggregation ---------
// grid (N, B), 512 threads.
__global__ __launch_bounds__(512) void gat_row_k(const float* __restrict__ A,
                                                 const float* __restrict__ bias,
                                                 float* __restrict__ out) {
    const int n = blockIdx.x;
    const int b = blockIdx.y;
    const int t = threadIdx.x;
    const int lane = t & 31;
    const int wid = t >> 5;
    const int h = t >> 6;
    const int u = t & 63;

    __shared__ int    s_idx[Nq];     // BYTE offsets (k * 2048)
    __shared__ float  s_w[Hq][WPAD];
    __shared__ float  s_red[16];
    __shared__ float  s_sum[Hq];
    __shared__ float  s_as[Hq];
    __shared__ float4 s_acc4[4][128];
    __shared__ int    s_cnt;
    if (t == 0) s_cnt = 0;
    if (t < Hq) s_as[t] = g_as[((size_t)b * Nq + n) * Hq + t];
    __syncthreads();

    // ---- Phase 1: compact edge list (store byte offset k*2048)
    const float* Arow = A + ((size_t)b * Nq + n) * Nq;
#pragma unroll
    for (int half = 0; half < 2; half++) {
        int c = half * 512 + t;
        bool e = Arow[c] > 0.0f;
        unsigned m = __ballot_sync(0xffffffffu, e);
        int cntw = __popc(m);
        int base = 0;
        if (lane == 0 && cntw) base = atomicAdd(&s_cnt, cntw);
        base = __shfl_sync(0xffffffffu, base, 0);
        if (e) {
            int off = __popc(m & ((1u << lane) - 1u));
            s_idx[base + off] = c << 11;       // k * 2048 bytes
        }
    }
    __syncthreads();
    const int cnt = s_cnt;

    // ---- Phase 2: per-(edge, head) leaky-relu logits
    const float* anb = g_an + (size_t)b * Nq * Hq;
    for (int p = t; p < cnt * Hq; p += 512) {
        int j = p >> 3;
        int hh = p & 7;
        int k = s_idx[j] >> 11;
        float x = s_as[hh] + anb[k * Hq + hh];
        s_w[hh][j] = (x > 0.0f) ? x : 0.2f * x;
    }
    __syncthreads();

    // ---- Phase 3: per-head max
    float lmax = -1e30f;
    for (int j = u; j < cnt; j += 64) lmax = fmaxf(lmax, s_w[h][j]);
#pragma unroll
    for (int o = 16; o; o >>= 1) lmax = fmaxf(lmax, __shfl_xor_sync(0xffffffffu, lmax, o));
    if (lane == 0) s_red[wid] = lmax;
    __syncthreads();
    const float m = fmaxf(s_red[2 * h], s_red[2 * h + 1]);
    __syncthreads();

    // ---- Phase 4: exp + per-head sum
    float lsum = 0.0f;
    for (int j = u; j < cnt; j += 64) {
        float w = __expf(s_w[h][j] - m);
        s_w[h][j] = w;
        lsum += w;
    }
#pragma unroll
    for (int o = 16; o; o >>= 1) lsum += __shfl_xor_sync(0xffffffffu, lsum, o);
    if (lane == 0) s_red[wid] = lsum;
    __syncthreads();
    if (lane == 0 && (wid & 1) == 0) s_sum[wid >> 1] = s_red[wid] + s_red[wid + 1];

    // ---- Phase 5: float4 gather, 4 edge sub-slots x 128 columns, unroll x2
    const int g  = t >> 7;       // 0..3
    const int c  = t & 127;      // float4 column
    const int hc = c >> 4;       // head for this column
    const char* fbase = (const char*)g_feat + ((size_t)b * Nq * HU) * 4 + (c << 4);
    float4 acc0 = make_float4(0.f, 0.f, 0.f, 0.f);
    float4 acc1 = make_float4(0.f, 0.f, 0.f, 0.f);
    int j = 0;
    for (; j + 8 <= cnt; j += 8) {
        int   o0 = s_idx[j + g];
        int   o1 = s_idx[j + g + 4];
        float w0 = s_w[hc][j + g];
        float w1 = s_w[hc][j + g + 4];
        float4 v0 = *(const float4*)(fbase + o0);
        float4 v1 = *(const float4*)(fbase + o1);
        acc0.x += w0 * v0.x; acc0.y += w0 * v0.y; acc0.z += w0 * v0.z; acc0.w += w0 * v0.w;
        acc1.x += w1 * v1.x; acc1.y += w1 * v1.y; acc1.z += w1 * v1.z; acc1.w += w1 * v1.w;
    }
    if (j + g < cnt) {
        int   o0 = s_idx[j + g];
        float w0 = s_w[hc][j + g];
        float4 v0 = *(const float4*)(fbase + o0);
        acc0.x += w0 * v0.x; acc0.y += w0 * v0.y; acc0.z += w0 * v0.z; acc0.w += w0 * v0.w;
    }
    if (j + g + 4 < cnt) {
        int   o1 = s_idx[j + g + 4];
        float w1 = s_w[hc][j + g + 4];
        float4 v1 = *(const float4*)(fbase + o1);
        acc1.x += w1 * v1.x; acc1.y += w1 * v1.y; acc1.z += w1 * v1.z; acc1.w += w1 * v1.w;
    }
    acc0.x += acc1.x; acc0.y += acc1.y; acc0.z += acc1.z; acc0.w += acc1.w;
    s_acc4[g][c] = acc0;
    __syncthreads();

    // ---- Phase 6: reduce sub-slots, add residual + bias, relu, store
    if (t < 128) {
        float4 a0 = s_acc4[0][t], a1 = s_acc4[1][t], a2 = s_acc4[2][t], a3 = s_acc4[3][t];
        float inv = 1.0f / s_sum[t >> 4];
        const size_t row4 = ((size_t)b * Nq + n) * 128 + t;
        float4 fr = ((const float4*)g_fres)[row4];
        float4 bi = ((const float4*)bias)[t];
        float4 o;
        o.x = fmaxf((a0.x + a1.x + a2.x + a3.x) * inv + fr.x + bi.x, 0.0f);
        o.y = fmaxf((a0.y + a1.y + a2.y + a3.y) * inv + fr.y + bi.y, 0.0f);
        o.z = fmaxf((a0.z + a1.z + a2.z + a3.z) * inv + fr.z + bi.z, 0.0f);
        o.w = fmaxf((a0.w + a1.w + a2.w + a3.w) * inv + fr.w + bi.w, 0.0f);
        ((float4*)out)[row4] = o;
    }
}

// -------------------------------- launch ---------------------------------
extern "C" void kernel_launch(void* const* d_in, const int* in_sizes, int n_in,
                              void* d_out, int out_size) {
    const float* X   = (const float*)d_in[0];
    const float* A   = (const float*)d_in[1];
    const float* Wk  = (const float*)d_in[2];
    const float* Wr  = (const float*)d_in[3];
    const float* aks = (const float*)d_in[4];
    const float* akn = (const float*)d_in[5];
    const float* bias = (const float*)d_in[6];
    float* out = (float*)d_out;

    dim3 ggrid(HU / 64, (Bq * Nq) / 128);
    sgemm_dual_k<<<ggrid, 256>>>(X, Wk, Wr);

    int nwarps = Bq * Nq * Hq;
    attn_logits_k<<<(nwarps * 32) / 256, 256>>>(aks, akn);

    gat_row_k<<<dim3(Nq, Bq), 512>>>(A, bias, out);
}

// round 5
// speedup vs baseline: 1.4837x; 1.0363x over previous
#include <cuda_runtime.h>
#include <cuda_fp16.h>
#include <cstdint>

#define Bq 8
#define Nq 1024
#define Dq 256
#define Hq 8
#define Uq 64
#define HU 512
#define WPAD 1025

// -------- scratch (device globals; no allocation in kernel_launch) --------
__device__ __half g_feat16[Bq * Nq * HU];  // features (fp16, for gather)
__device__ float  g_fres[Bq * Nq * HU];    // residual features (fp32)
__device__ float  g_as[Bq * Nq * Hq];      // attn_self logits
__device__ float  g_an[Bq * Nq * Hq];      // attn_neigh logits

// ---- Kernel 1: fused dual SGEMM + attention logits + fp16 feature write --
// Tile 64x64, K-tile 16, 256 threads, 4x4x2 acc/thread. n-tile == one head.
__global__ __launch_bounds__(256) void sgemm_dual_k(const float* __restrict__ Xg,
                                                    const float* __restrict__ Wk,
                                                    const float* __restrict__ Wr,
                                                    const float* __restrict__ aks,
                                                    const float* __restrict__ akn) {
    __shared__ float As[16][64];
    __shared__ float BsK[16][64];
    __shared__ float BsR[16][64];

    const int tid = threadIdx.x;
    const int m0 = blockIdx.y * 64;
    const int n0 = blockIdx.x * 64;
    const int h  = blockIdx.x;          // head owning this n-tile
    const int tx = tid & 15;
    const int ty = tid >> 4;

    float aK[4][4], aR[4][4];
#pragma unroll
    for (int i = 0; i < 4; i++)
#pragma unroll
        for (int j = 0; j < 4; j++) { aK[i][j] = 0.0f; aR[i][j] = 0.0f; }

    const int a_m  = tid >> 2;    // 0..63
    const int a_k4 = tid & 3;     // k chunk *4
    const int b_k  = tid >> 4;    // 0..15
    const int b_n4 = tid & 15;

    for (int k0 = 0; k0 < Dq; k0 += 16) {
        float4 v = *(const float4*)&Xg[(size_t)(m0 + a_m) * Dq + k0 + a_k4 * 4];
        As[a_k4 * 4 + 0][a_m] = v.x;
        As[a_k4 * 4 + 1][a_m] = v.y;
        As[a_k4 * 4 + 2][a_m] = v.z;
        As[a_k4 * 4 + 3][a_m] = v.w;
        size_t widx = (size_t)(k0 + b_k) * HU + n0 + b_n4 * 4;
        *(float4*)&BsK[b_k][b_n4 * 4] = *(const float4*)&Wk[widx];
        *(float4*)&BsR[b_k][b_n4 * 4] = *(const float4*)&Wr[widx];
        __syncthreads();
#pragma unroll
        for (int k = 0; k < 16; k++) {
            float4 a  = *(const float4*)&As[k][ty * 4];
            float4 bk = *(const float4*)&BsK[k][tx * 4];
            float4 br = *(const float4*)&BsR[k][tx * 4];
            float av[4]  = {a.x, a.y, a.z, a.w};
            float bKv[4] = {bk.x, bk.y, bk.z, bk.w};
            float bRv[4] = {br.x, br.y, br.z, br.w};
#pragma unroll
            for (int i = 0; i < 4; i++)
#pragma unroll
                for (int j = 0; j < 4; j++) {
                    aK[i][j] += av[i] * bKv[j];
                    aR[i][j] += av[i] * bRv[j];
                }
        }
        __syncthreads();
    }

    // ---- epilogue A: attention logits for this head (reduce across tx) ----
    float ks[4], kn[4];
#pragma unroll
    for (int j = 0; j < 4; j++) {
        ks[j] = __ldg(&aks[h * Uq + tx * 4 + j]);
        kn[j] = __ldg(&akn[h * Uq + tx * 4 + j]);
    }
#pragma unroll
    for (int i = 0; i < 4; i++) {
        int m = m0 + ty * 4 + i;
        float sS = aK[i][0] * ks[0] + aK[i][1] * ks[1] + aK[i][2] * ks[2] + aK[i][3] * ks[3];
        float sN = aK[i][0] * kn[0] + aK[i][1] * kn[1] + aK[i][2] * kn[2] + aK[i][3] * kn[3];
#pragma unroll
        for (int o = 8; o; o >>= 1) {
            sS += __shfl_xor_sync(0xffffffffu, sS, o);
            sN += __shfl_xor_sync(0xffffffffu, sN, o);
        }
        if (tx == 0) {
            g_as[m * Hq + h] = sS;
            g_an[m * Hq + h] = sN;
        }
    }

    // ---- epilogue B: write fp16 features + fp32 residual ----
#pragma unroll
    for (int i = 0; i < 4; i++) {
        size_t oidx = (size_t)(m0 + ty * 4 + i) * HU + n0 + tx * 4;
        __half2* d16 = (__half2*)&g_feat16[oidx];
        d16[0] = __floats2half2_rn(aK[i][0], aK[i][1]);
        d16[1] = __floats2half2_rn(aK[i][2], aK[i][3]);
        *(float4*)&g_fres[oidx] = make_float4(aR[i][0], aR[i][1], aR[i][2], aR[i][3]);
    }
}

// --------- Kernel 2: fused all-heads masked softmax + fp16 aggregation ----
// grid (N, B), 512 threads.
__global__ __launch_bounds__(512) void gat_row_k(const float* __restrict__ A,
                                                 const float* __restrict__ bias,
                                                 float* __restrict__ out) {
    const int n = blockIdx.x;
    const int b = blockIdx.y;
    const int t = threadIdx.x;
    const int lane = t & 31;
    const int wid = t >> 5;
    const int h = t >> 6;
    const int u = t & 63;

    __shared__ int   s_idx[Nq];      // BYTE offsets (k * 1024, fp16 rows)
    __shared__ float s_w[Hq][WPAD];  // logits/weights; REUSED as acc after ph5
    __shared__ float s_red[16];
    __shared__ float s_sum[Hq];
    __shared__ float s_as[Hq];
    __shared__ int   s_cnt;
    if (t == 0) s_cnt = 0;
    if (t < Hq) s_as[t] = g_as[((size_t)b * Nq + n) * Hq + t];
    __syncthreads();

    // ---- Phase 1: compact edge list (byte offsets into fp16 feature rows)
    const float* Arow = A + ((size_t)b * Nq + n) * Nq;
#pragma unroll
    for (int half = 0; half < 2; half++) {
        int c = half * 512 + t;
        bool e = Arow[c] > 0.0f;
        unsigned m = __ballot_sync(0xffffffffu, e);
        int cntw = __popc(m);
        int base = 0;
        if (lane == 0 && cntw) base = atomicAdd(&s_cnt, cntw);
        base = __shfl_sync(0xffffffffu, base, 0);
        if (e) {
            int off = __popc(m & ((1u << lane) - 1u));
            s_idx[base + off] = c << 10;      // k * 1024 bytes
        }
    }
    __syncthreads();
    const int cnt = s_cnt;

    // ---- Phase 2: per-(edge, head) leaky-relu logits
    const float* anb = g_an + (size_t)b * Nq * Hq;
    for (int p = t; p < cnt * Hq; p += 512) {
        int j = p >> 3;
        int hh = p & 7;
        int k = s_idx[j] >> 10;
        float x = s_as[hh] + anb[k * Hq + hh];
        s_w[hh][j] = (x > 0.0f) ? x : 0.2f * x;
    }
    __syncthreads();

    // ---- Phase 3: per-head max
    float lmax = -1e30f;
    for (int j = u; j < cnt; j += 64) lmax = fmaxf(lmax, s_w[h][j]);
#pragma unroll
    for (int o = 16; o; o >>= 1) lmax = fmaxf(lmax, __shfl_xor_sync(0xffffffffu, lmax, o));
    if (lane == 0) s_red[wid] = lmax;
    __syncthreads();
    const float m = fmaxf(s_red[2 * h], s_red[2 * h + 1]);
    __syncthreads();

    // ---- Phase 4: exp + per-head sum
    float lsum = 0.0f;
    for (int j = u; j < cnt; j += 64) {
        float w = __expf(s_w[h][j] - m);
        s_w[h][j] = w;
        lsum += w;
    }
#pragma unroll
    for (int o = 16; o; o >>= 1) lsum += __shfl_xor_sync(0xffffffffu, lsum, o);
    if (lane == 0) s_red[wid] = lsum;
    __syncthreads();
    if (lane == 0 && (wid & 1) == 0) s_sum[wid >> 1] = s_red[wid] + s_red[wid + 1];

    // ---- Phase 5: fp16 gather. 8 edge sub-slots x 64 uint4-columns.
    const int g  = t >> 6;     // 0..7 edge sub-slot
    const int c  = t & 63;     // 16-byte column (8 halves)
    const int hc = c >> 3;     // head owning this column
    const char* fbase = (const char*)g_feat16 + (size_t)b * Nq * 1024 + (c << 4);
    float acc[8];
#pragma unroll
    for (int r = 0; r < 8; r++) acc[r] = 0.0f;

    int j = 0;
    for (; j + 16 <= cnt; j += 16) {
        int   oa = s_idx[j + g];
        int   ob = s_idx[j + 8 + g];
        float wa = s_w[hc][j + g];
        float wb = s_w[hc][j + 8 + g];
        uint4 va = *(const uint4*)(fbase + oa);
        uint4 vb = *(const uint4*)(fbase + ob);
        {
            float2 f0 = __half22float2(*(__half2*)&va.x);
            float2 f1 = __half22float2(*(__half2*)&va.y);
            float2 f2 = __half22float2(*(__half2*)&va.z);
            float2 f3 = __half22float2(*(__half2*)&va.w);
            acc[0] += wa * f0.x; acc[1] += wa * f0.y;
            acc[2] += wa * f1.x; acc[3] += wa * f1.y;
            acc[4] += wa * f2.x; acc[5] += wa * f2.y;
            acc[6] += wa * f3.x; acc[7] += wa * f3.y;
        }
        {
            float2 f0 = __half22float2(*(__half2*)&vb.x);
            float2 f1 = __half22float2(*(__half2*)&vb.y);
            float2 f2 = __half22float2(*(__half2*)&vb.z);
            float2 f3 = __half22float2(*(__half2*)&vb.w);
            acc[0] += wb * f0.x; acc[1] += wb * f0.y;
            acc[2] += wb * f1.x; acc[3] += wb * f1.y;
            acc[4] += wb * f2.x; acc[5] += wb * f2.y;
            acc[6] += wb * f3.x; acc[7] += wb * f3.y;
        }
    }
    for (; j + g < cnt; j += 8) {
        int   oa = s_idx[j + g];
        float wa = s_w[hc][j + g];
        uint4 va = *(const uint4*)(fbase + oa);
        float2 f0 = __half22float2(*(__half2*)&va.x);
        float2 f1 = __half22float2(*(__half2*)&va.y);
        float2 f2 = __half22float2(*(__half2*)&va.z);
        float2 f3 = __half22float2(*(__half2*)&va.w);
        acc[0] += wa * f0.x; acc[1] += wa * f0.y;
        acc[2] += wa * f1.x; acc[3] += wa * f1.y;
        acc[4] += wa * f2.x; acc[5] += wa * f2.y;
        acc[6] += wa * f3.x; acc[7] += wa * f3.y;
    }
    __syncthreads();            // s_w reads done; reuse region as accumulator
    float* s_accf = &s_w[0][0]; // [8 slots][64 cols][8 vals] = 16KB
#pragma unroll
    for (int r = 0; r < 8; r++) s_accf[(g * 64 + c) * 8 + r] = acc[r];
    __syncthreads();

    // ---- Phase 6: reduce slots, add residual + bias, relu, store
    {
        float a = 0.0f;
#pragma unroll
        for (int g2 = 0; g2 < 8; g2++) a += s_accf[g2 * 512 + t];
        float inv = 1.0f / s_sum[h];
        const size_t oidx = ((size_t)b * Nq + n) * HU + t;
        float o = a * inv + g_fres[oidx] + bias[t];
        out[oidx] = fmaxf(o, 0.0f);
    }
}

// -------------------------------- launch ---------------------------------
extern "C" void kernel_launch(void* const* d_in, const int* in_sizes, int n_in,
                              void* d_out, int out_size) {
    const float* X   = (const float*)d_in[0];
    const float* A   = (const float*)d_in[1];
    const float* Wk  = (const float*)d_in[2];
    const float* Wr  = (const float*)d_in[3];
    const float* aks = (const float*)d_in[4];
    const float* akn = (const float*)d_in[5];
    const float* bias = (const float*)d_in[6];
    float* out = (float*)d_out;

    sgemm_dual_k<<<dim3(HU / 64, (Bq * Nq) / 64), 256>>>(X, Wk, Wr, aks, akn);
    gat_row_k<<<dim3(Nq, Bq), 512>>>(A, bias, out);
}

// round 7
// speedup vs baseline: 2.0156x; 1.3585x over previous
#include <cuda_runtime.h>
#include <cuda_fp16.h>
#include <cuda_bf16.h>
#include <cstdint>

#define Bq 8
#define Nq 1024
#define Dq 256
#define Hq 8
#define Uq 64
#define HU 512
#define WPAD 1025

// -------- scratch (device globals; no allocation in kernel_launch) --------
__device__ __half g_feat16[Bq * Nq * HU];     // features (fp16)
__device__ __half g_fres16[Bq * Nq * HU];     // residual features (fp16)
__device__ float  g_as[Bq * Nq * Hq];
__device__ float  g_an[Bq * Nq * Hq];
// stacked weights: K'=768 rows x 1024 cols (n<512: Wk, else Wr)
// rows [0,256)=hi, [256,512)=hi, [512,768)=lo  (pairs with A = [hi, lo, hi])
__device__ __nv_bfloat16 gWb[768 * 1024];

// ------------------------- helpers ---------------------------------------
__device__ __forceinline__ uint32_t smem_u32(const void* p) {
    uint32_t a;
    asm("{ .reg .u64 t; cvta.to.shared.u64 t, %1; cvt.u32.u64 %0, t; }" : "=r"(a) : "l"(p));
    return a;
}
__device__ __forceinline__ uint32_t pkb2(__nv_bfloat16 a, __nv_bfloat16 b) {
    __nv_bfloat162 p = __halves2bfloat162(a, b);
    return *reinterpret_cast<uint32_t*>(&p);
}
__device__ __forceinline__ void ldsm_x4(uint32_t addr, uint32_t& r0, uint32_t& r1,
                                        uint32_t& r2, uint32_t& r3) {
    asm volatile("ldmatrix.sync.aligned.m8n8.x4.shared.b16 {%0,%1,%2,%3}, [%4];"
                 : "=r"(r0), "=r"(r1), "=r"(r2), "=r"(r3) : "r"(addr));
}
__device__ __forceinline__ void ldsm_x2t(uint32_t addr, uint32_t& r0, uint32_t& r1) {
    asm volatile("ldmatrix.sync.aligned.m8n8.x2.trans.shared.b16 {%0,%1}, [%2];"
                 : "=r"(r0), "=r"(r1) : "r"(addr));
}
__device__ __forceinline__ void mma16816(float* d, uint32_t a0, uint32_t a1,
                                         uint32_t a2, uint32_t a3,
                                         uint32_t b0, uint32_t b1) {
    asm volatile(
        "mma.sync.aligned.m16n8k16.row.col.f32.bf16.bf16.f32 "
        "{%0,%1,%2,%3}, {%4,%5,%6,%7}, {%8,%9}, {%0,%1,%2,%3};"
        : "+f"(d[0]), "+f"(d[1]), "+f"(d[2]), "+f"(d[3])
        : "r"(a0), "r"(a1), "r"(a2), "r"(a3), "r"(b0), "r"(b1));
}

// ------------- Kernel 0: W -> stacked bf16 [768][1024] -------------------
__global__ __launch_bounds__(256) void wconv_k(const float* __restrict__ Wk,
                                               const float* __restrict__ Wr) {
    int idx = blockIdx.x * 256 + threadIdx.x;     // 786432
    int kv = idx >> 10;
    int nc = idx & 1023;
    int part = kv >> 8;
    int k = kv & 255;
    const float* W = (nc >> 9) ? Wr : Wk;
    float x = W[(size_t)k * HU + (nc & 511)];
    __nv_bfloat16 hb = __float2bfloat16_rn(x);
    __nv_bfloat16 o = (part == 2) ? __float2bfloat16_rn(x - __bfloat162float(hb)) : hb;
    gWb[idx] = o;
}

// --- Kernel 1: mma.sync split-bf16 GEMM + logits + fp16 writes -----------
// grid (8 n-blocks, 64 m-blocks), 256 threads (8 warps, 2m x 4n).
#define ASTRIDE 72
#define BSTRIDE 136
__global__ __launch_bounds__(256) void gemm_mma_k(const float* __restrict__ Xg,
                                                  const float* __restrict__ aks,
                                                  const float* __restrict__ akn) {
    __shared__ __nv_bfloat16 As[128 * ASTRIDE];   // [m=128][k=64] pad 8
    __shared__ __nv_bfloat16 Bs[64 * BSTRIDE];    // [k=64][n=128] pad 8
    __shared__ float s_part[4][128][2];           // [warp_n][row][S/N]
    __shared__ float s_ak[128], s_an[128];

    const int tid = threadIdx.x;
    const int l   = tid & 31;
    const int wid = tid >> 5;
    const int wm  = wid & 1;        // warp m (0..1) -> 64 rows
    const int wn  = wid >> 1;       // warp n (0..3) -> 32 cols
    const int bx  = blockIdx.x;     // n-block: 0..3 feat(Wk), 4..7 res(Wr)
    const int by  = blockIdx.y;     // m-block

    const uint32_t aBase = smem_u32(As);
    const uint32_t bBase = smem_u32(Bs);

    float acc[4][4][4];
#pragma unroll
    for (int i = 0; i < 4; i++)
#pragma unroll
        for (int j = 0; j < 4; j++)
#pragma unroll
            for (int r = 0; r < 4; r++) acc[i][j][r] = 0.0f;

    for (int ic = 0; ic < 12; ic++) {
        const int part = ic >> 2;           // 0:hi 1:lo 2:hi (A side)
        const int k0 = (ic & 3) * 64;       // source X k offset
        // ---- A: 128 x 64 fp32 -> bf16 (hi or lo)
#pragma unroll
        for (int i = 0; i < 8; i++) {
            int slot = i * 256 + tid;       // 2048 float4 slots
            int row = slot >> 4;
            int c4 = slot & 15;
            float4 v = *(const float4*)&Xg[(size_t)(by * 128 + row) * Dq + k0 + c4 * 4];
            __nv_bfloat16 o0, o1, o2, o3;
            __nv_bfloat16 h0 = __float2bfloat16_rn(v.x);
            __nv_bfloat16 h1 = __float2bfloat16_rn(v.y);
            __nv_bfloat16 h2 = __float2bfloat16_rn(v.z);
            __nv_bfloat16 h3 = __float2bfloat16_rn(v.w);
            if (part == 1) {
                o0 = __float2bfloat16_rn(v.x - __bfloat162float(h0));
                o1 = __float2bfloat16_rn(v.y - __bfloat162float(h1));
                o2 = __float2bfloat16_rn(v.z - __bfloat162float(h2));
                o3 = __float2bfloat16_rn(v.w - __bfloat162float(h3));
            } else {
                o0 = h0; o1 = h1; o2 = h2; o3 = h3;
            }
            *(uint2*)&As[row * ASTRIDE + c4 * 4] = make_uint2(pkb2(o0, o1), pkb2(o2, o3));
        }
        // ---- B: stacked gWb rows [ic*64, +64), cols [bx*128, +128)
#pragma unroll
        for (int i = 0; i < 4; i++) {
            int slot = i * 256 + tid;       // 1024 uint4 slots
            int r = slot >> 4;
            int c8 = slot & 15;
            uint4 v = *(const uint4*)&gWb[(size_t)(ic * 64 + r) * 1024 + bx * 128 + c8 * 8];
            *(uint4*)&Bs[r * BSTRIDE + c8 * 8] = v;
        }
        __syncthreads();
        // ---- 4 k-steps of 16
#pragma unroll
        for (int kk = 0; kk < 4; kk++) {
            uint32_t a[4][4], b[4][2];
#pragma unroll
            for (int mf = 0; mf < 4; mf++) {
                int row = wm * 64 + mf * 16 + (l & 7) + ((l >> 3) & 1) * 8;
                int col = kk * 16 + (l >> 4) * 8;
                ldsm_x4(aBase + (row * ASTRIDE + col) * 2,
                        a[mf][0], a[mf][1], a[mf][2], a[mf][3]);
            }
#pragma unroll
            for (int nf = 0; nf < 4; nf++) {
                int lr = l & 15;
                int row = kk * 16 + (lr & 7) + (lr >> 3) * 8;
                int col = wn * 32 + nf * 8;
                ldsm_x2t(bBase + (row * BSTRIDE + col) * 2, b[nf][0], b[nf][1]);
            }
#pragma unroll
            for (int mf = 0; mf < 4; mf++)
#pragma unroll
                for (int nf = 0; nf < 4; nf++)
                    mma16816(acc[mf][nf], a[mf][0], a[mf][1], a[mf][2], a[mf][3],
                             b[nf][0], b[nf][1]);
        }
        __syncthreads();
    }

    // ---------------- epilogue ----------------
    if (bx < 4 && tid < 128) {
        s_ak[tid] = aks[bx * 128 + tid];
        s_an[tid] = akn[bx * 128 + tid];
    }
    __syncthreads();

#pragma unroll
    for (int mf = 0; mf < 4; mf++) {
        int r_lo = wm * 64 + mf * 16 + (l >> 2);
        int m_lo = by * 128 + r_lo;
        int m_hi = m_lo + 8;
        float sSl = 0.f, sSh = 0.f, sNl = 0.f, sNh = 0.f;
#pragma unroll
        for (int nf = 0; nf < 4; nf++) {
            int col_l = wn * 32 + nf * 8 + (l & 3) * 2;
            float c0 = acc[mf][nf][0], c1 = acc[mf][nf][1];
            float c2 = acc[mf][nf][2], c3 = acc[mf][nf][3];
            if (bx < 4) {
                int col = bx * 128 + col_l;
                *(__half2*)&g_feat16[(size_t)m_lo * HU + col] = __floats2half2_rn(c0, c1);
                *(__half2*)&g_feat16[(size_t)m_hi * HU + col] = __floats2half2_rn(c2, c3);
                sSl += c0 * s_ak[col_l] + c1 * s_ak[col_l + 1];
                sSh += c2 * s_ak[col_l] + c3 * s_ak[col_l + 1];
                sNl += c0 * s_an[col_l] + c1 * s_an[col_l + 1];
                sNh += c2 * s_an[col_l] + c3 * s_an[col_l + 1];
            } else {
                int col = (bx - 4) * 128 + col_l;
                *(__half2*)&g_fres16[(size_t)m_lo * HU + col] = __floats2half2_rn(c0, c1);
                *(__half2*)&g_fres16[(size_t)m_hi * HU + col] = __floats2half2_rn(c2, c3);
            }
        }
        if (bx < 4) {
#pragma unroll
            for (int o = 1; o <= 2; o <<= 1) {
                sSl += __shfl_xor_sync(0xffffffffu, sSl, o);
                sSh += __shfl_xor_sync(0xffffffffu, sSh, o);
                sNl += __shfl_xor_sync(0xffffffffu, sNl, o);
                sNh += __shfl_xor_sync(0xffffffffu, sNh, o);
            }
            if ((l & 3) == 0) {
                s_part[wn][r_lo][0] = sSl;
                s_part[wn][r_lo][1] = sNl;
                s_part[wn][r_lo + 8][0] = sSh;
                s_part[wn][r_lo + 8][1] = sNh;
            }
        }
    }
    __syncthreads();
    if (bx < 4) {
        int row = tid >> 1;
        int sn = tid & 1;
        float v0 = s_part[0][row][sn] + s_part[1][row][sn];
        float v1 = s_part[2][row][sn] + s_part[3][row][sn];
        int m = by * 128 + row;
        float* dst = sn ? g_an : g_as;
        dst[(size_t)m * Hq + bx * 2] = v0;
        dst[(size_t)m * Hq + bx * 2 + 1] = v1;
    }
}

// --------- Kernel 2: fused all-heads masked softmax + fp16 aggregation ----
__global__ __launch_bounds__(512) void gat_row_k(const float* __restrict__ A,
                                                 const float* __restrict__ bias,
                                                 float* __restrict__ out) {
    const int n = blockIdx.x;
    const int b = blockIdx.y;
    const int t = threadIdx.x;
    const int lane = t & 31;
    const int wid = t >> 5;
    const int h = t >> 6;
    const int u = t & 63;

    __shared__ int   s_idx[Nq];
    __shared__ float s_w[Hq][WPAD];
    __shared__ float s_red[16];
    __shared__ float s_sum[Hq];
    __shared__ float s_as[Hq];
    __shared__ int   s_cnt;
    if (t == 0) s_cnt = 0;
    if (t < Hq) s_as[t] = g_as[((size_t)b * Nq + n) * Hq + t];
    __syncthreads();

    const float* Arow = A + ((size_t)b * Nq + n) * Nq;
#pragma unroll
    for (int half = 0; half < 2; half++) {
        int c = half * 512 + t;
        bool e = Arow[c] > 0.0f;
        unsigned m = __ballot_sync(0xffffffffu, e);
        int cntw = __popc(m);
        int base = 0;
        if (lane == 0 && cntw) base = atomicAdd(&s_cnt, cntw);
        base = __shfl_sync(0xffffffffu, base, 0);
        if (e) {
            int off = __popc(m & ((1u << lane) - 1u));
            s_idx[base + off] = c << 10;
        }
    }
    __syncthreads();
    const int cnt = s_cnt;

    const float* anb = g_an + (size_t)b * Nq * Hq;
    for (int p = t; p < cnt * Hq; p += 512) {
        int j = p >> 3;
        int hh = p & 7;
        int k = s_idx[j] >> 10;
        float x = s_as[hh] + anb[k * Hq + hh];
        s_w[hh][j] = (x > 0.0f) ? x : 0.2f * x;
    }
    __syncthreads();

    float lmax = -1e30f;
    for (int j = u; j < cnt; j += 64) lmax = fmaxf(lmax, s_w[h][j]);
#pragma unroll
    for (int o = 16; o; o >>= 1) lmax = fmaxf(lmax, __shfl_xor_sync(0xffffffffu, lmax, o));
    if (lane == 0) s_red[wid] = lmax;
    __syncthreads();
    const float m = fmaxf(s_red[2 * h], s_red[2 * h + 1]);
    __syncthreads();

    float lsum = 0.0f;
    for (int j = u; j < cnt; j += 64) {
        float w = __expf(s_w[h][j] - m);
        s_w[h][j] = w;
        lsum += w;
    }
#pragma unroll
    for (int o = 16; o; o >>= 1) lsum += __shfl_xor_sync(0xffffffffu, lsum, o);
    if (lane == 0) s_red[wid] = lsum;
    __syncthreads();
    if (lane == 0 && (wid & 1) == 0) s_sum[wid >> 1] = s_red[wid] + s_red[wid + 1];

    const int g  = t >> 6;
    const int c  = t & 63;
    const int hc = c >> 3;
    const char* fbase = (const char*)g_feat16 + (size_t)b * Nq * 1024 + (c << 4);
    float acc[8];
#pragma unroll
    for (int r = 0; r < 8; r++) acc[r] = 0.0f;

    int j = 0;
    for (; j + 16 <= cnt; j += 16) {
        int   oa = s_idx[j + g];
        int   ob = s_idx[j + 8 + g];
        float wa = s_w[hc][j + g];
        float wb = s_w[hc][j + 8 + g];
        uint4 va = *(const uint4*)(fbase + oa);
        uint4 vb = *(const uint4*)(fbase + ob);
        {
            float2 f0 = __half22float2(*(__half2*)&va.x);
            float2 f1 = __half22float2(*(__half2*)&va.y);
            float2 f2 = __half22float2(*(__half2*)&va.z);
            float2 f3 = __half22float2(*(__half2*)&va.w);
            acc[0] += wa * f0.x; acc[1] += wa * f0.y;
            acc[2] += wa * f1.x; acc[3] += wa * f1.y;
            acc[4] += wa * f2.x; acc[5] += wa * f2.y;
            acc[6] += wa * f3.x; acc[7] += wa * f3.y;
        }
        {
            float2 f0 = __half22float2(*(__half2*)&vb.x);
            float2 f1 = __half22float2(*(__half2*)&vb.y);
            float2 f2 = __half22float2(*(__half2*)&vb.z);
            float2 f3 = __half22float2(*(__half2*)&vb.w);
            acc[0] += wb * f0.x; acc[1] += wb * f0.y;
            acc[2] += wb * f1.x; acc[3] += wb * f1.y;
            acc[4] += wb * f2.x; acc[5] += wb * f2.y;
            acc[6] += wb * f3.x; acc[7] += wb * f3.y;
        }
    }
    for (; j + g < cnt; j += 8) {
        int   oa = s_idx[j + g];
        float wa = s_w[hc][j + g];
        uint4 va = *(const uint4*)(fbase + oa);
        float2 f0 = __half22float2(*(__half2*)&va.x);
        float2 f1 = __half22float2(*(__half2*)&va.y);
        float2 f2 = __half22float2(*(__half2*)&va.z);
        float2 f3 = __half22float2(*(__half2*)&va.w);
        acc[0] += wa * f0.x; acc[1] += wa * f0.y;
        acc[2] += wa * f1.x; acc[3] += wa * f1.y;
        acc[4] += wa * f2.x; acc[5] += wa * f2.y;
        acc[6] += wa * f3.x; acc[7] += wa * f3.y;
    }
    __syncthreads();
    float* s_accf = &s_w[0][0];
#pragma unroll
    for (int r = 0; r < 8; r++) s_accf[(g * 64 + c) * 8 + r] = acc[r];
    __syncthreads();

    {
        float a = 0.0f;
#pragma unroll
        for (int g2 = 0; g2 < 8; g2++) a += s_accf[g2 * 512 + t];
        float inv = 1.0f / s_sum[h];
        const size_t oidx = ((size_t)b * Nq + n) * HU + t;
        float o = a * inv + __half2float(g_fres16[oidx]) + bias[t];
        out[oidx] = fmaxf(o, 0.0f);
    }
}

// -------------------------------- launch ---------------------------------
extern "C" void kernel_launch(void* const* d_in, const int* in_sizes, int n_in,
                              void* d_out, int out_size) {
    const float* X    = (const float*)d_in[0];
    const float* A    = (const float*)d_in[1];
    const float* Wk   = (const float*)d_in[2];
    const float* Wr   = (const float*)d_in[3];
    const float* aks  = (const float*)d_in[4];
    const float* akn  = (const float*)d_in[5];
    const float* bias = (const float*)d_in[6];
    float* out = (float*)d_out;

    wconv_k<<<768 * 1024 / 256, 256>>>(Wk, Wr);
    gemm_mma_k<<<dim3(8, 64), 256>>>(X, aks, akn);
    gat_row_k<<<dim3(Nq, Bq), 512>>>(A, bias, out);
}